// round 1
// baseline (speedup 1.0000x reference)
#include <cuda_runtime.h>

#define DIM   256
#define NCLS  20
#define MAXN  50000
#define MAXE  800000
#define BN_EPS 1e-5f

// ---------------- scratch (device globals: no allocation allowed) ----------
__device__ float g_bufA[(size_t)MAXN * DIM];
__device__ float g_bufB[(size_t)MAXN * DIM];
__device__ int   g_cnt[MAXN];
__device__ int   g_rowptr[MAXN + 1];
__device__ int   g_cursor[MAXN];
__device__ int   g_adj[MAXE];
__device__ float g_dinv[MAXN];
__device__ float g_bnsum[2 * DIM];
__device__ int   g_is64;

// ---------------- init: zero counters + detect edge dtype ------------------
__global__ void k_init(const void* eiv, int E, int n) {
    int i = blockIdx.x * blockDim.x + threadIdx.x;
    if (i < n) g_cnt[i] = 0;
    if (i < 2 * DIM) g_bnsum[i] = 0.f;
    if (i == 0) {
        // If the buffer is int32 pairs, reading as int64 yields values >= 2^32
        // (upper word = next index, ~never 0 for 64 samples). Range-check.
        const long long* p = (const long long*)eiv;
        int ok = 1;
        int m = E < 64 ? E : 64;
        for (int k = 0; k < m; k++) {
            long long v = p[k];
            if (v < 0 || v >= (long long)n) { ok = 0; break; }
        }
        g_is64 = ok;
    }
}

// ---------------- CSR build ------------------------------------------------
__global__ void k_count(const void* eiv, int E) {
    int e = blockIdx.x * blockDim.x + threadIdx.x;
    if (e >= E) return;
    int d;
    if (g_is64) d = (int)((const long long*)eiv)[(size_t)E + e];
    else        d = ((const int*)eiv)[(size_t)E + e];
    atomicAdd(&g_cnt[d], 1);
}

__global__ void k_scan(int n) {
    __shared__ int part[1024];
    int t = threadIdx.x;
    int chunk = (n + 1023) >> 10;
    int beg = t * chunk;
    int end = beg + chunk; if (end > n) end = n;
    int s = 0;
    for (int i = beg; i < end; i++) s += g_cnt[i];
    part[t] = s;
    __syncthreads();
    for (int off = 1; off < 1024; off <<= 1) {
        int v = 0;
        if (t >= off) v = part[t - off];
        __syncthreads();
        part[t] += v;
        __syncthreads();
    }
    int run = (t == 0) ? 0 : part[t - 1];
    for (int i = beg; i < end; i++) {
        g_rowptr[i] = run;
        g_cursor[i] = run;
        run += g_cnt[i];
    }
    if (beg < n && end == n) g_rowptr[n] = run;
}

__global__ void k_fill(const void* eiv, int E) {
    int e = blockIdx.x * blockDim.x + threadIdx.x;
    if (e >= E) return;
    int s, d;
    if (g_is64) {
        const long long* p = (const long long*)eiv;
        s = (int)p[e]; d = (int)p[(size_t)E + e];
    } else {
        const int* p = (const int*)eiv;
        s = p[e]; d = p[(size_t)E + e];
    }
    int pos = atomicAdd(&g_cursor[d], 1);
    g_adj[pos] = s;
}

__global__ void k_dinv(int n) {
    int i = blockIdx.x * blockDim.x + threadIdx.x;
    if (i < n) g_dinv[i] = rsqrtf((float)g_cnt[i] + 1.0f);
}

// ---------------- fp32 tiled GEMM: C = A[MxK] @ B[KxN] (+bias)(+relu) ------
__global__ __launch_bounds__(256) void k_sgemm(
    const float* __restrict__ A, const float* __restrict__ B,
    const float* __restrict__ bias, float* __restrict__ Cm,
    int M, int K, int N, int relu)
{
    const int BM = 128, BKT = 8, TM = 8, TN = 8;
    __shared__ float As[BKT][BM];
    __shared__ float Bs[BKT][128];
    int tid  = threadIdx.x;
    int row0 = blockIdx.y * BM;
    int col0 = blockIdx.x * 128;
    int tx = (tid & 15) * TN;
    int ty = (tid >> 4) * TM;
    int a_r = tid >> 1;
    int a_c = (tid & 1) * 4;
    int b_r = tid >> 5;
    int b_c = (tid & 31) * 4;

    float acc[TM][TN];
#pragma unroll
    for (int i = 0; i < TM; i++)
#pragma unroll
        for (int j = 0; j < TN; j++) acc[i][j] = 0.f;

    for (int k0 = 0; k0 < K; k0 += BKT) {
#pragma unroll
        for (int i = 0; i < 4; i++) {
            int gr = row0 + a_r, gc = k0 + a_c + i;
            As[a_c + i][a_r] = (gr < M && gc < K) ? A[(size_t)gr * K + gc] : 0.f;
        }
        {
            int gr = k0 + b_r;
            if (gr < K) {
                const float* Brow = B + (size_t)gr * N + col0 + b_c;
#pragma unroll
                for (int i = 0; i < 4; i++)
                    Bs[b_r][b_c + i] = (col0 + b_c + i < N) ? Brow[i] : 0.f;
            } else {
#pragma unroll
                for (int i = 0; i < 4; i++) Bs[b_r][b_c + i] = 0.f;
            }
        }
        __syncthreads();
#pragma unroll
        for (int kk = 0; kk < BKT; kk++) {
            float ra[TM], rb[TN];
#pragma unroll
            for (int i = 0; i < TM; i++) ra[i] = As[kk][ty + i];
#pragma unroll
            for (int j = 0; j < TN; j++) rb[j] = Bs[kk][tx + j];
#pragma unroll
            for (int i = 0; i < TM; i++)
#pragma unroll
                for (int j = 0; j < TN; j++) acc[i][j] += ra[i] * rb[j];
        }
        __syncthreads();
    }

#pragma unroll
    for (int i = 0; i < TM; i++) {
        int r = row0 + ty + i;
        if (r >= M) continue;
#pragma unroll
        for (int j = 0; j < TN; j++) {
            int c = col0 + tx + j;
            if (c >= N) continue;
            float v = acc[i][j];
            if (bias) v += bias[c];
            if (relu) v = fmaxf(v, 0.f);
            Cm[(size_t)r * N + c] = v;
        }
    }
}

// ---------------- GCN aggregation (warp per node, CSR gather) --------------
// out[i] = relu( dinv_i * sum_{s in adj(i)} dinv_s * t[s]  + dinv_i^2 * t[i] + b )
__global__ void k_aggregate(const float* __restrict__ t,
                            const float* __restrict__ bias,
                            float* __restrict__ out, int n)
{
    int warp = (blockIdx.x * blockDim.x + threadIdx.x) >> 5;
    int lane = threadIdx.x & 31;
    if (warp >= n) return;
    int node = warp;
    float dd  = g_dinv[node];
    int beg = g_rowptr[node], end = g_rowptr[node + 1];
    float4 a0 = {0.f, 0.f, 0.f, 0.f}, a1 = {0.f, 0.f, 0.f, 0.f};
    for (int j = beg; j < end; j++) {
        int s = g_adj[j];
        float ds = g_dinv[s];
        const float4* r = (const float4*)(t + (size_t)s * DIM);
        float4 v0 = r[lane], v1 = r[lane + 32];
        a0.x += ds * v0.x; a0.y += ds * v0.y; a0.z += ds * v0.z; a0.w += ds * v0.w;
        a1.x += ds * v1.x; a1.y += ds * v1.y; a1.z += ds * v1.z; a1.w += ds * v1.w;
    }
    const float4* sr = (const float4*)(t + (size_t)node * DIM);
    float4 s0 = sr[lane], s1 = sr[lane + 32];
    const float4* b4 = (const float4*)bias;
    float4 bb0 = b4[lane], bb1 = b4[lane + 32];
    float dd2 = dd * dd;
    float4 o0, o1;
    o0.x = fmaxf(dd * a0.x + dd2 * s0.x + bb0.x, 0.f);
    o0.y = fmaxf(dd * a0.y + dd2 * s0.y + bb0.y, 0.f);
    o0.z = fmaxf(dd * a0.z + dd2 * s0.z + bb0.z, 0.f);
    o0.w = fmaxf(dd * a0.w + dd2 * s0.w + bb0.w, 0.f);
    o1.x = fmaxf(dd * a1.x + dd2 * s1.x + bb1.x, 0.f);
    o1.y = fmaxf(dd * a1.y + dd2 * s1.y + bb1.y, 0.f);
    o1.z = fmaxf(dd * a1.z + dd2 * s1.z + bb1.z, 0.f);
    o1.w = fmaxf(dd * a1.w + dd2 * s1.w + bb1.w, 0.f);
    float4* ow = (float4*)(out + (size_t)node * DIM);
    ow[lane] = o0; ow[lane + 32] = o1;
}

// ---------------- BatchNorm statistics -------------------------------------
__global__ void k_bnreduce(const float* __restrict__ h, int n) {
    int f = threadIdx.x;          // 256 threads = one feature each
    float s = 0.f, q = 0.f;
    for (int r = blockIdx.x; r < n; r += gridDim.x) {
        float v = h[(size_t)r * DIM + f];
        s += v; q += v * v;
    }
    atomicAdd(&g_bnsum[f], s);
    atomicAdd(&g_bnsum[DIM + f], q);
}

// ---------------- fused BN + ReLU + mlp2 + softmax --------------------------
__global__ __launch_bounds__(256) void k_final(
    const float* __restrict__ h, const float* __restrict__ w2,
    const float* __restrict__ b2, const float* __restrict__ gamma,
    const float* __restrict__ beta, float* __restrict__ out, int n)
{
    __shared__ float sW[DIM * NCLS];     // 20 KB
    __shared__ float sA[DIM], sB[DIM];
    __shared__ float sb2[NCLS];
    __shared__ float sH[8][DIM];         // 8 KB
    int tid = threadIdx.x;
    for (int i = tid; i < DIM * NCLS; i += 256) sW[i] = w2[i];
    if (tid < NCLS) sb2[tid] = b2[tid];
    {
        float invn = 1.0f / (float)n;
        float mu  = g_bnsum[tid] * invn;
        float var = g_bnsum[DIM + tid] * invn - mu * mu;
        float rs  = rsqrtf(var + BN_EPS);
        float a   = rs * gamma[tid];
        sA[tid] = a;
        sB[tid] = beta[tid] - mu * a;
    }
    __syncthreads();

    int warp = tid >> 5, lane = tid & 31;
    int node = blockIdx.x * 8 + warp;
    if (node >= n) return;

    const float* hr = h + (size_t)node * DIM;
#pragma unroll
    for (int k = 0; k < 8; k++) {
        int f = lane + 32 * k;
        float v = hr[f] * sA[f] + sB[f];
        sH[warp][f] = fmaxf(v, 0.f);
    }
    __syncwarp();

    float logit = -1e30f;
    if (lane < NCLS) {
        float acc = sb2[lane];
#pragma unroll 8
        for (int f = 0; f < DIM; f++) acc += sH[warp][f] * sW[f * NCLS + lane];
        logit = acc;
    }
    float m = logit;
#pragma unroll
    for (int off = 16; off; off >>= 1) m = fmaxf(m, __shfl_xor_sync(0xffffffffu, m, off));
    float e = (lane < NCLS) ? __expf(logit - m) : 0.f;
    float ssum = e;
#pragma unroll
    for (int off = 16; off; off >>= 1) ssum += __shfl_xor_sync(0xffffffffu, ssum, off);
    if (lane < NCLS) out[(size_t)node * NCLS + lane] = e / ssum;
}

// ---------------- host ------------------------------------------------------
extern "C" void kernel_launch(void* const* d_in, const int* in_sizes, int n_in,
                              void* d_out, int out_size)
{
    const float* x    = (const float*)d_in[0];
    const void*  ei   = d_in[1];
    const float* linw = (const float*)d_in[2];
    const float* c1w  = (const float*)d_in[3];
    const float* c1b  = (const float*)d_in[4];
    const float* c2w  = (const float*)d_in[5];
    const float* c2b  = (const float*)d_in[6];
    const float* m1w  = (const float*)d_in[7];
    const float* m1b  = (const float*)d_in[8];
    const float* gam  = (const float*)d_in[9];
    const float* bet  = (const float*)d_in[10];
    const float* m2w  = (const float*)d_in[11];
    const float* m2b  = (const float*)d_in[12];
    float* out = (float*)d_out;

    int Dd = in_sizes[4];                 // 256 (conv1_b)
    int G  = in_sizes[2] / Dd;            // 1002
    int n  = in_sizes[0] / G;             // 50000
    int E  = in_sizes[1] / 2;             // 800000

    float *bufA, *bufB;
    cudaGetSymbolAddress((void**)&bufA, g_bufA);
    cudaGetSymbolAddress((void**)&bufB, g_bufB);

    const int tpb = 256;
    int initN = (n > 2 * DIM) ? n : 2 * DIM;
    k_init<<<(initN + tpb - 1) / tpb, tpb>>>(ei, E, n);
    k_count<<<(E + tpb - 1) / tpb, tpb>>>(ei, E);
    k_scan<<<1, 1024>>>(n);
    k_fill<<<(E + tpb - 1) / tpb, tpb>>>(ei, E);
    k_dinv<<<(n + tpb - 1) / tpb, tpb>>>(n);

    dim3 blk(256);
    dim3 grd((DIM + 127) / 128, (n + 127) / 128);
    // encoder + GCN
    k_sgemm<<<grd, blk>>>(x,    linw, nullptr, bufA, n, G,   DIM, 0);
    k_sgemm<<<grd, blk>>>(bufA, c1w,  nullptr, bufB, n, DIM, DIM, 0);
    k_aggregate<<<(n + 7) / 8, 256>>>(bufB, c1b, bufA, n);
    k_sgemm<<<grd, blk>>>(bufA, c2w,  nullptr, bufB, n, DIM, DIM, 0);
    k_aggregate<<<(n + 7) / 8, 256>>>(bufB, c2b, bufA, n);
    // decoder
    k_sgemm<<<grd, blk>>>(bufA, m1w, m1b, bufB, n, DIM, DIM, 0);
    k_bnreduce<<<256, DIM>>>(bufB, n);
    k_final<<<(n + 7) / 8, 256>>>(bufB, m2w, m2b, gam, bet, out, n);
}

// round 5
// speedup vs baseline: 2.3569x; 2.3569x over previous
#include <cuda_runtime.h>
#include <cuda_bf16.h>
#include <cstdint>

#define DIM   256
#define NCLS  20
#define MAXN  50000
#define MAXE  800000
#define BN_EPS 1e-5f
#define KPAD0 1024

// ==================== device scratch =======================================
__device__ float g_bufA[(size_t)MAXN * DIM];
__device__ float g_bufB[(size_t)MAXN * DIM];
__device__ int   g_cnt[MAXN];
__device__ int   g_rowptr[MAXN + 1];
__device__ int   g_cursor[MAXN];
__device__ int   g_adj[MAXE];
__device__ float g_dinv[MAXN];
__device__ float g_bnsum[2 * DIM];
__device__ int   g_is64;
// weight splits: [N=256][Kpad] bf16 as u16; lin (Kpad=1024) + 3 x (Kpad=256)
#define WOFF0 0
#define WOFF1 (256 * 1024)
#define WOFF2 (WOFF1 + 256 * 256)
#define WOFF3 (WOFF2 + 256 * 256)
#define WTOT  (WOFF3 + 256 * 256)
__device__ unsigned short g_whi[WTOT];
__device__ unsigned short g_wlo[WTOT];

// ==================== PTX helpers (non-'a' only!) ==========================
__device__ __forceinline__ uint32_t smem_u32(const void* p) {
    uint32_t a;
    asm("{ .reg .u64 t; cvta.to.shared.u64 t, %1; cvt.u32.u64 %0, t; }" : "=r"(a) : "l"(p));
    return a;
}
#define LDSM_X4(r, addr) \
    asm volatile("ldmatrix.sync.aligned.m8n8.x4.shared.b16 {%0,%1,%2,%3}, [%4];" \
        : "=r"((r)[0]), "=r"((r)[1]), "=r"((r)[2]), "=r"((r)[3]) : "r"(addr))
#define MMA_BF16(cv, a, b0v, b1v) \
    asm volatile("mma.sync.aligned.m16n8k16.row.col.f32.bf16.bf16.f32 " \
        "{%0,%1,%2,%3}, {%4,%5,%6,%7}, {%8,%9}, {%0,%1,%2,%3};" \
        : "+f"((cv)[0]), "+f"((cv)[1]), "+f"((cv)[2]), "+f"((cv)[3]) \
        : "r"((a)[0]), "r"((a)[1]), "r"((a)[2]), "r"((a)[3]), "r"(b0v), "r"(b1v))

// ==================== init / CSR build =====================================
__global__ void k_init(const void* eiv, int E, int n) {
    int i = blockIdx.x * blockDim.x + threadIdx.x;
    if (i < n) g_cnt[i] = 0;
    if (i < 2 * DIM) g_bnsum[i] = 0.f;
    if (i == 0) {
        const long long* p = (const long long*)eiv;
        int ok = 1;
        int m = E < 64 ? E : 64;
        for (int k = 0; k < m; k++) {
            long long v = p[k];
            if (v < 0 || v >= (long long)n) { ok = 0; break; }
        }
        g_is64 = ok;
    }
}
__global__ void k_count(const void* eiv, int E) {
    int e = blockIdx.x * blockDim.x + threadIdx.x;
    if (e >= E) return;
    int d;
    if (g_is64) d = (int)((const long long*)eiv)[(size_t)E + e];
    else        d = ((const int*)eiv)[(size_t)E + e];
    atomicAdd(&g_cnt[d], 1);
}
__global__ void k_scan(int n) {
    __shared__ int part[1024];
    int t = threadIdx.x;
    int chunk = (n + 1023) >> 10;
    int beg = t * chunk;
    int end = beg + chunk; if (end > n) end = n;
    int s = 0;
    for (int i = beg; i < end; i++) s += g_cnt[i];
    part[t] = s;
    __syncthreads();
    for (int off = 1; off < 1024; off <<= 1) {
        int v = 0;
        if (t >= off) v = part[t - off];
        __syncthreads();
        part[t] += v;
        __syncthreads();
    }
    int run = (t == 0) ? 0 : part[t - 1];
    for (int i = beg; i < end; i++) {
        g_rowptr[i] = run;
        g_cursor[i] = run;
        run += g_cnt[i];
    }
    if (beg < n && end == n) g_rowptr[n] = run;
}
__global__ void k_fill(const void* eiv, int E) {
    int e = blockIdx.x * blockDim.x + threadIdx.x;
    if (e >= E) return;
    int s, d;
    if (g_is64) {
        const long long* p = (const long long*)eiv;
        s = (int)p[e]; d = (int)p[(size_t)E + e];
    } else {
        const int* p = (const int*)eiv;
        s = p[e]; d = p[(size_t)E + e];
    }
    int pos = atomicAdd(&g_cursor[d], 1);
    g_adj[pos] = s;
}
__global__ void k_dinv(int n) {
    int i = blockIdx.x * blockDim.x + threadIdx.x;
    if (i < n) g_dinv[i] = rsqrtf((float)g_cnt[i] + 1.0f);
}

// ==================== weight prep: fp32 [K,256] -> bf16 split [256,Kpad] ===
__global__ void k_wprep(const float* __restrict__ w, int K, int Kpad,
                        unsigned short* __restrict__ hi, unsigned short* __restrict__ lo)
{
    int i = blockIdx.x * blockDim.x + threadIdx.x;
    int total = 256 * Kpad;
    if (i >= total) return;
    int nidx = i / Kpad;
    int k = i - nidx * Kpad;
    float f = (k < K) ? w[(size_t)k * 256 + nidx] : 0.f;
    unsigned u = __float_as_uint(f);
    hi[i] = (unsigned short)(u >> 16);
    float hf = __uint_as_float(u & 0xFFFF0000u);
    __nv_bfloat16 lb = __float2bfloat16(f - hf);
    lo[i] = __bfloat16_as_ushort(lb);
}

// ==================== bf16 split-precision tensor-core GEMM =================
// C[M,256] = A[M,K] @ W[K,256]; A fp32 split inline; W pre-split [256][Kpad].
// CTA tile 128x128 (grid.y = 2 halves of N); 8 warps 4(M)x2(N), warp 32x64.
// BK=32, single-buffer smem, pitch 80B (conflict-free ldmatrix).
#define SM_P 80
#define SM_A_H 0
#define SM_A_L 10240
#define SM_B_H 20480
#define SM_B_L 30720
__global__ __launch_bounds__(256, 2) void k_mmagemm(
    const float* __restrict__ A,
    const unsigned short* __restrict__ Bhi,
    const unsigned short* __restrict__ Blo,
    const float* __restrict__ bias,
    float* __restrict__ Cm,
    int M, int K, int Kpad, int relu)
{
    __shared__ __align__(16) unsigned char sm[40960];
    uint32_t sb = smem_u32(sm);
    int tid = threadIdx.x, wid = tid >> 5, lane = tid & 31;
    int row0 = blockIdx.x * 128;
    int c0   = blockIdx.y * 128;
    int wm = wid & 3, wn = wid >> 2;

    float cacc[2][8][4];
#pragma unroll
    for (int a = 0; a < 2; a++)
#pragma unroll
        for (int b = 0; b < 8; b++)
#pragma unroll
            for (int d = 0; d < 4; d++) cacc[a][b][d] = 0.f;

    // loader mapping: 2 threads per row, 16 elems each
    int arow  = tid >> 1;
    int ahalf = (tid & 1) * 16;
    const float* Arow = A + (size_t)(row0 + arow) * K;
    bool aOK = (row0 + arow) < M;
    const unsigned short* BHrow = Bhi + (size_t)(c0 + arow) * Kpad + ahalf;
    const unsigned short* BLrow = Blo + (size_t)(c0 + arow) * Kpad + ahalf;
    uint32_t aStore = sb + (uint32_t)(arow * SM_P + ahalf * 2);
    uint32_t bStore = sb + (uint32_t)(arow * SM_P + ahalf * 2);

    // ldmatrix lane addresses
    uint32_t aOff = (uint32_t)((wm * 32 + (lane & 15)) * SM_P + (lane >> 4) * 16);
    uint32_t bOff = (uint32_t)((wn * 64 + (lane & 7) + ((lane >> 4) & 1) * 8) * SM_P
                               + ((lane >> 3) & 1) * 16);

    for (int kb = 0; kb < Kpad; kb += 32) {
        // ---- global loads into registers
        // NOTE: A rows are only 8-byte aligned when K is odd*2 (K=1002:
        // row stride 4008 B, 4008 % 16 == 8) -> float2, never float4.
        float av[16];
        if (aOK && kb + ahalf + 16 <= K) {
#pragma unroll
            for (int j = 0; j < 8; j++) {
                float2 v = *(const float2*)(Arow + kb + ahalf + j * 2);
                av[j * 2] = v.x; av[j * 2 + 1] = v.y;
            }
        } else {
#pragma unroll
            for (int j = 0; j < 16; j++) {
                int gc = kb + ahalf + j;
                av[j] = (aOK && gc < K) ? Arow[gc] : 0.f;
            }
        }
        uint4 bh0 = *(const uint4*)(BHrow + kb);
        uint4 bh1 = *(const uint4*)(BHrow + kb + 8);
        uint4 bl0 = *(const uint4*)(BLrow + kb);
        uint4 bl1 = *(const uint4*)(BLrow + kb + 8);

        __syncthreads();   // previous iteration's compute done

        // ---- A convert + store (hi/lo)
#pragma unroll
        for (int j = 0; j < 8; j++) {
            unsigned u0 = __float_as_uint(av[j * 2]);
            unsigned u1 = __float_as_uint(av[j * 2 + 1]);
            unsigned hp = __byte_perm(u0, u1, 0x7632);
            float l0 = av[j * 2]     - __uint_as_float(u0 & 0xFFFF0000u);
            float l1 = av[j * 2 + 1] - __uint_as_float(u1 & 0xFFFF0000u);
            __nv_bfloat162 lp2 = __floats2bfloat162_rn(l0, l1);
            unsigned lp = *(unsigned*)&lp2;
            asm volatile("st.shared.b32 [%0], %1;" :: "r"(aStore + SM_A_H + j * 4), "r"(hp));
            asm volatile("st.shared.b32 [%0], %1;" :: "r"(aStore + SM_A_L + j * 4), "r"(lp));
        }
        // ---- B store
        asm volatile("st.shared.v4.b32 [%0], {%1,%2,%3,%4};"
                     :: "r"(bStore + SM_B_H), "r"(bh0.x), "r"(bh0.y), "r"(bh0.z), "r"(bh0.w));
        asm volatile("st.shared.v4.b32 [%0], {%1,%2,%3,%4};"
                     :: "r"(bStore + SM_B_H + 16), "r"(bh1.x), "r"(bh1.y), "r"(bh1.z), "r"(bh1.w));
        asm volatile("st.shared.v4.b32 [%0], {%1,%2,%3,%4};"
                     :: "r"(bStore + SM_B_L), "r"(bl0.x), "r"(bl0.y), "r"(bl0.z), "r"(bl0.w));
        asm volatile("st.shared.v4.b32 [%0], {%1,%2,%3,%4};"
                     :: "r"(bStore + SM_B_L + 16), "r"(bl1.x), "r"(bl1.y), "r"(bl1.z), "r"(bl1.w));

        __syncthreads();   // tiles ready

        // ---- compute: 2 k-frags x (4 n-pairs x 2 m-frags x 3 products)
#pragma unroll
        for (int kf = 0; kf < 2; kf++) {
            uint32_t ah[2][4], al[2][4];
#pragma unroll
            for (int mf = 0; mf < 2; mf++) {
                uint32_t addr = sb + aOff + (uint32_t)(mf * 16 * SM_P + kf * 32);
                LDSM_X4(ah[mf], addr + SM_A_H);
                LDSM_X4(al[mf], addr + SM_A_L);
            }
#pragma unroll
            for (int np = 0; np < 4; np++) {
                uint32_t bh[4], bl[4];
                uint32_t addr = sb + bOff + (uint32_t)(np * 16 * SM_P + kf * 32);
                LDSM_X4(bh, addr + SM_B_H);
                LDSM_X4(bl, addr + SM_B_L);
#pragma unroll
                for (int mf = 0; mf < 2; mf++) {
                    MMA_BF16(cacc[mf][np * 2],     ah[mf], bh[0], bh[1]);
                    MMA_BF16(cacc[mf][np * 2],     ah[mf], bl[0], bl[1]);
                    MMA_BF16(cacc[mf][np * 2],     al[mf], bh[0], bh[1]);
                    MMA_BF16(cacc[mf][np * 2 + 1], ah[mf], bh[2], bh[3]);
                    MMA_BF16(cacc[mf][np * 2 + 1], ah[mf], bl[2], bl[3]);
                    MMA_BF16(cacc[mf][np * 2 + 1], al[mf], bh[2], bh[3]);
                }
            }
        }
    }

    // ---- epilogue
    int g = lane >> 2, tq = lane & 3;
#pragma unroll
    for (int mf = 0; mf < 2; mf++) {
        int r = row0 + wm * 32 + mf * 16 + g;
#pragma unroll
        for (int nf = 0; nf < 8; nf++) {
            int cc = c0 + wn * 64 + nf * 8 + tq * 2;
            float b0 = 0.f, b1 = 0.f;
            if (bias) { b0 = __ldg(bias + cc); b1 = __ldg(bias + cc + 1); }
            float v0 = cacc[mf][nf][0] + b0, v1 = cacc[mf][nf][1] + b1;
            float v2 = cacc[mf][nf][2] + b0, v3 = cacc[mf][nf][3] + b1;
            if (relu) {
                v0 = fmaxf(v0, 0.f); v1 = fmaxf(v1, 0.f);
                v2 = fmaxf(v2, 0.f); v3 = fmaxf(v3, 0.f);
            }
            if (r < M)     *(float2*)(Cm + (size_t)r * 256 + cc)       = make_float2(v0, v1);
            if (r + 8 < M) *(float2*)(Cm + (size_t)(r + 8) * 256 + cc) = make_float2(v2, v3);
        }
    }
}

// ==================== GCN aggregation (warp per node) ======================
__global__ void k_aggregate(const float* __restrict__ t,
                            const float* __restrict__ bias,
                            float* __restrict__ out, int n)
{
    int warp = (blockIdx.x * blockDim.x + threadIdx.x) >> 5;
    int lane = threadIdx.x & 31;
    if (warp >= n) return;
    int node = warp;
    float dd  = g_dinv[node];
    int beg = g_rowptr[node], end = g_rowptr[node + 1];
    float4 a0 = {0.f, 0.f, 0.f, 0.f}, a1 = {0.f, 0.f, 0.f, 0.f};
    for (int j = beg; j < end; j++) {
        int s = g_adj[j];
        float ds = g_dinv[s];
        const float4* r = (const float4*)(t + (size_t)s * DIM);
        float4 v0 = r[lane], v1 = r[lane + 32];
        a0.x += ds * v0.x; a0.y += ds * v0.y; a0.z += ds * v0.z; a0.w += ds * v0.w;
        a1.x += ds * v1.x; a1.y += ds * v1.y; a1.z += ds * v1.z; a1.w += ds * v1.w;
    }
    const float4* sr = (const float4*)(t + (size_t)node * DIM);
    float4 s0 = sr[lane], s1 = sr[lane + 32];
    const float4* b4 = (const float4*)bias;
    float4 bb0 = b4[lane], bb1 = b4[lane + 32];
    float dd2 = dd * dd;
    float4 o0, o1;
    o0.x = fmaxf(dd * a0.x + dd2 * s0.x + bb0.x, 0.f);
    o0.y = fmaxf(dd * a0.y + dd2 * s0.y + bb0.y, 0.f);
    o0.z = fmaxf(dd * a0.z + dd2 * s0.z + bb0.z, 0.f);
    o0.w = fmaxf(dd * a0.w + dd2 * s0.w + bb0.w, 0.f);
    o1.x = fmaxf(dd * a1.x + dd2 * s1.x + bb1.x, 0.f);
    o1.y = fmaxf(dd * a1.y + dd2 * s1.y + bb1.y, 0.f);
    o1.z = fmaxf(dd * a1.z + dd2 * s1.z + bb1.z, 0.f);
    o1.w = fmaxf(dd * a1.w + dd2 * s1.w + bb1.w, 0.f);
    float4* ow = (float4*)(out + (size_t)node * DIM);
    ow[lane] = o0; ow[lane + 32] = o1;
}

// ==================== BN stats + fused final ===============================
__global__ void k_bnreduce(const float* __restrict__ h, int n) {
    int f = threadIdx.x;
    float s = 0.f, q = 0.f;
    for (int r = blockIdx.x; r < n; r += gridDim.x) {
        float v = h[(size_t)r * DIM + f];
        s += v; q += v * v;
    }
    atomicAdd(&g_bnsum[f], s);
    atomicAdd(&g_bnsum[DIM + f], q);
}

__global__ __launch_bounds__(256) void k_final(
    const float* __restrict__ h, const float* __restrict__ w2,
    const float* __restrict__ b2, const float* __restrict__ gamma,
    const float* __restrict__ beta, float* __restrict__ out, int n)
{
    __shared__ float sW[DIM * NCLS];
    __shared__ float sA[DIM], sB[DIM];
    __shared__ float sb2[NCLS];
    __shared__ float sH[8][DIM];
    int tid = threadIdx.x;
    for (int i = tid; i < DIM * NCLS; i += 256) sW[i] = w2[i];
    if (tid < NCLS) sb2[tid] = b2[tid];
    {
        float invn = 1.0f / (float)n;
        float mu  = g_bnsum[tid] * invn;
        float var = g_bnsum[DIM + tid] * invn - mu * mu;
        float rs  = rsqrtf(var + BN_EPS);
        float a   = rs * gamma[tid];
        sA[tid] = a;
        sB[tid] = beta[tid] - mu * a;
    }
    __syncthreads();

    int warp = tid >> 5, lane = tid & 31;
    int node = blockIdx.x * 8 + warp;
    if (node >= n) return;

    const float* hr = h + (size_t)node * DIM;
#pragma unroll
    for (int k = 0; k < 8; k++) {
        int f = lane + 32 * k;
        float v = hr[f] * sA[f] + sB[f];
        sH[warp][f] = fmaxf(v, 0.f);
    }
    __syncwarp();

    float logit = -1e30f;
    if (lane < NCLS) {
        float acc = sb2[lane];
#pragma unroll 8
        for (int f = 0; f < DIM; f++) acc += sH[warp][f] * sW[f * NCLS + lane];
        logit = acc;
    }
    float m = logit;
#pragma unroll
    for (int off = 16; off; off >>= 1) m = fmaxf(m, __shfl_xor_sync(0xffffffffu, m, off));
    float e = (lane < NCLS) ? __expf(logit - m) : 0.f;
    float ssum = e;
#pragma unroll
    for (int off = 16; off; off >>= 1) ssum += __shfl_xor_sync(0xffffffffu, ssum, off);
    if (lane < NCLS) out[(size_t)node * NCLS + lane] = e / ssum;
}

// ==================== host =================================================
extern "C" void kernel_launch(void* const* d_in, const int* in_sizes, int n_in,
                              void* d_out, int out_size)
{
    const float* x    = (const float*)d_in[0];
    const void*  ei   = d_in[1];
    const float* linw = (const float*)d_in[2];
    const float* c1w  = (const float*)d_in[3];
    const float* c1b  = (const float*)d_in[4];
    const float* c2w  = (const float*)d_in[5];
    const float* c2b  = (const float*)d_in[6];
    const float* m1w  = (const float*)d_in[7];
    const float* m1b  = (const float*)d_in[8];
    const float* gam  = (const float*)d_in[9];
    const float* bet  = (const float*)d_in[10];
    const float* m2w  = (const float*)d_in[11];
    const float* m2b  = (const float*)d_in[12];
    float* out = (float*)d_out;

    int Dd = in_sizes[4];                 // 256
    int G  = in_sizes[2] / Dd;            // 1002
    int n  = in_sizes[0] / G;             // 50000
    int E  = in_sizes[1] / 2;             // 800000

    float *bufA, *bufB;
    unsigned short *whi, *wlo;
    cudaGetSymbolAddress((void**)&bufA, g_bufA);
    cudaGetSymbolAddress((void**)&bufB, g_bufB);
    cudaGetSymbolAddress((void**)&whi, g_whi);
    cudaGetSymbolAddress((void**)&wlo, g_wlo);

    const int tpb = 256;
    int initN = (n > 2 * DIM) ? n : 2 * DIM;
    k_init<<<(initN + tpb - 1) / tpb, tpb>>>(ei, E, n);
    k_count<<<(E + tpb - 1) / tpb, tpb>>>(ei, E);
    k_scan<<<1, 1024>>>(n);
    k_fill<<<(E + tpb - 1) / tpb, tpb>>>(ei, E);
    k_dinv<<<(n + tpb - 1) / tpb, tpb>>>(n);

    // weight prep (bf16 split, transposed to [N,Kpad])
    k_wprep<<<(256 * KPAD0 + tpb - 1) / tpb, tpb>>>(linw, G,   KPAD0, whi + WOFF0, wlo + WOFF0);
    k_wprep<<<(256 * 256 + tpb - 1) / tpb,  tpb>>>(c1w,  256, 256,   whi + WOFF1, wlo + WOFF1);
    k_wprep<<<(256 * 256 + tpb - 1) / tpb,  tpb>>>(c2w,  256, 256,   whi + WOFF2, wlo + WOFF2);
    k_wprep<<<(256 * 256 + tpb - 1) / tpb,  tpb>>>(m1w,  256, 256,   whi + WOFF3, wlo + WOFF3);

    dim3 grd((n + 127) / 128, 2);
    // encoder + GCN
    k_mmagemm<<<grd, 256>>>(x,    whi + WOFF0, wlo + WOFF0, nullptr, bufA, n, G,   KPAD0, 0);
    k_mmagemm<<<grd, 256>>>(bufA, whi + WOFF1, wlo + WOFF1, nullptr, bufB, n, 256, 256,   0);
    k_aggregate<<<(n + 7) / 8, 256>>>(bufB, c1b, bufA, n);
    k_mmagemm<<<grd, 256>>>(bufA, whi + WOFF2, wlo + WOFF2, nullptr, bufB, n, 256, 256,   0);
    k_aggregate<<<(n + 7) / 8, 256>>>(bufB, c2b, bufA, n);
    // decoder
    k_mmagemm<<<grd, 256>>>(bufA, whi + WOFF3, wlo + WOFF3, m1b, bufB, n, 256, 256, 0);
    k_bnreduce<<<256, DIM>>>(bufB, n);
    k_final<<<(n + 7) / 8, 256>>>(bufB, m2w, m2b, gam, bet, out, n);
}